// round 1
// baseline (speedup 1.0000x reference)
#include <cuda_runtime.h>
#include <math.h>

#define B_ 2
#define S_ 2048
#define E_ 1024
#define H_ 16
#define D_ 64
#define M_ (B_*S_)   // 4096 rows

// Scratch (allocation-free): q/k/v in [B,H,S,D] layout, attn in [B,S,E]
__device__ float g_q[(size_t)B_*H_*S_*D_];
__device__ float g_k[(size_t)B_*H_*S_*D_];
__device__ float g_v[(size_t)B_*H_*S_*D_];
__device__ float g_attn[(size_t)B_*S_*E_];

// ---------------------------------------------------------------------------
// GEMM: C = A[M,K=E] @ W[N=E,K=E]^T + bias.  128x128 tile, BK=16, 8x8/thread.
// SPLIT=true writes C into [B,H,S,D] layout (head split), else row-major [M,E].
// ---------------------------------------------------------------------------
template<bool SPLIT>
__global__ __launch_bounds__(256, 2) void gemm_bias_kernel(
    const float* __restrict__ A, const float* __restrict__ W,
    const float* __restrict__ bias, float* __restrict__ C)
{
    __shared__ float As[16][132];   // [k][m], pad 4 -> 2-way store conflicts only
    __shared__ float Bs[16][132];   // [k][n]
    const int tid = threadIdx.x;
    const int bm = blockIdx.y * 128;
    const int bn = blockIdx.x * 128;
    const int tx = tid & 15;
    const int ty = tid >> 4;

    float acc[8][8];
#pragma unroll
    for (int i = 0; i < 8; i++)
#pragma unroll
        for (int j = 0; j < 8; j++) acc[i][j] = 0.f;

    for (int k0 = 0; k0 < E_; k0 += 16) {
#pragma unroll
        for (int t = 0; t < 2; t++) {
            int fid = tid + t * 256;        // 512 float4 per operand tile
            int r   = fid >> 2;             // 0..127
            int c4  = (fid & 3) * 4;        // 0,4,8,12
            float4 va = *(const float4*)(A + (size_t)(bm + r) * E_ + k0 + c4);
            As[c4+0][r] = va.x; As[c4+1][r] = va.y; As[c4+2][r] = va.z; As[c4+3][r] = va.w;
            float4 vb = *(const float4*)(W + (size_t)(bn + r) * E_ + k0 + c4);
            Bs[c4+0][r] = vb.x; Bs[c4+1][r] = vb.y; Bs[c4+2][r] = vb.z; Bs[c4+3][r] = vb.w;
        }
        __syncthreads();
#pragma unroll
        for (int k = 0; k < 16; k++) {
            float a[8], b[8];
            *(float4*)&a[0] = *(float4*)&As[k][ty*4];
            *(float4*)&a[4] = *(float4*)&As[k][ty*4+64];
            *(float4*)&b[0] = *(float4*)&Bs[k][tx*4];
            *(float4*)&b[4] = *(float4*)&Bs[k][tx*4+64];
#pragma unroll
            for (int i = 0; i < 8; i++)
#pragma unroll
                for (int j = 0; j < 8; j++)
                    acc[i][j] = fmaf(a[i], b[j], acc[i][j]);
        }
        __syncthreads();
    }

#pragma unroll
    for (int ih = 0; ih < 2; ih++) {
#pragma unroll
        for (int i = 0; i < 4; i++) {
            int m  = bm + ih*64 + ty*4 + i;
            int bb = m >> 11;          // / S_
            int ss = m & (S_-1);
#pragma unroll
            for (int jh = 0; jh < 2; jh++) {
                int n0 = bn + jh*64 + tx*4;
                float4 bv = *(const float4*)(bias + n0);
                float4 r;
                r.x = acc[ih*4+i][jh*4+0] + bv.x;
                r.y = acc[ih*4+i][jh*4+1] + bv.y;
                r.z = acc[ih*4+i][jh*4+2] + bv.z;
                r.w = acc[ih*4+i][jh*4+3] + bv.w;
                if (SPLIT) {
                    int h = n0 >> 6;          // head (D_=64)
                    int d = n0 & 63;
                    *(float4*)(C + ((size_t)(bb * H_ + h) * S_ + ss) * D_ + d) = r;
                } else {
                    *(float4*)(C + (size_t)m * E_ + n0) = r;
                }
            }
        }
    }
}

// ---------------------------------------------------------------------------
// Causal flash attention, fp32. One block per (bh, q-tile of 64 rows).
// 256 threads: tx=tid&15 covers 64 cols (4 each), ty=tid>>4 covers 64 rows.
// Qt/KP store transposed [d][row] so score inner loop is pure LDS.128.
// KP is reused as P[row][k] for the PV product. 48KB static smem exactly.
// ---------------------------------------------------------------------------
__global__ __launch_bounds__(256, 2) void attn_kernel()
{
    __shared__ float Qt[64][64];   // Qt[d][row]
    __shared__ float KP[64][64];   // Kt[d][col]  then  P[row][k]
    __shared__ float Vs[64][64];   // V[k][d]

    const int qt = blockIdx.x;     // 0..31
    const int bh = blockIdx.y;     // 0..31 = b*H + h
    const int b  = bh >> 4;
    const int h  = bh & 15;
    const int tid = threadIdx.x;
    const int tx = tid & 15;
    const int ty = tid >> 4;

    const float* qbase = g_q + (size_t)bh * S_ * D_ + (size_t)qt * 64 * D_;
    const float* kbase = g_k + (size_t)bh * S_ * D_;
    const float* vbase = g_v + (size_t)bh * S_ * D_;

    // Load Q transposed (once). Uncoalesced gmem read, conflict-free smem store.
#pragma unroll
    for (int t = 0; t < 4; t++) {
        int fid = tid + t * 256;          // 0..1023
        int row = fid & 63;
        int d4  = (fid >> 6) * 4;         // 0,4,...,60
        float4 v = *(const float4*)(qbase + row * D_ + d4);
        Qt[d4+0][row] = v.x; Qt[d4+1][row] = v.y; Qt[d4+2][row] = v.z; Qt[d4+3][row] = v.w;
    }

    float o[4][4];
    float m_i[4], l_i[4];
#pragma unroll
    for (int i = 0; i < 4; i++) {
        m_i[i] = -1e30f; l_i[i] = 0.f;
#pragma unroll
        for (int j = 0; j < 4; j++) o[i][j] = 0.f;
    }
    const float scale = 0.125f;   // 1/sqrt(64)

    for (int kt = 0; kt <= qt; kt++) {
        __syncthreads();   // protect KP(=P of prev iter) + first-iter Qt
        const float* kb = kbase + (size_t)kt * 64 * D_;
        const float* vb = vbase + (size_t)kt * 64 * D_;
#pragma unroll
        for (int t = 0; t < 4; t++) {
            int fid = tid + t * 256;
            int col = fid & 63;
            int d4  = (fid >> 6) * 4;
            float4 v = *(const float4*)(kb + col * D_ + d4);
            KP[d4+0][col] = v.x; KP[d4+1][col] = v.y; KP[d4+2][col] = v.z; KP[d4+3][col] = v.w;
            int vr  = fid >> 4;           // 0..63
            int vc4 = (fid & 15) * 4;
            float4 w = *(const float4*)(vb + vr * D_ + vc4);
            *(float4*)&Vs[vr][vc4] = w;
        }
        __syncthreads();

        // S = Q K^T (64x64 tile), 4x4 per thread
        float s[4][4];
#pragma unroll
        for (int i = 0; i < 4; i++)
#pragma unroll
            for (int j = 0; j < 4; j++) s[i][j] = 0.f;
#pragma unroll
        for (int d = 0; d < 64; d++) {
            float4 a  = *(float4*)&Qt[d][ty*4];
            float4 bq = *(float4*)&KP[d][tx*4];
            s[0][0] = fmaf(a.x, bq.x, s[0][0]); s[0][1] = fmaf(a.x, bq.y, s[0][1]);
            s[0][2] = fmaf(a.x, bq.z, s[0][2]); s[0][3] = fmaf(a.x, bq.w, s[0][3]);
            s[1][0] = fmaf(a.y, bq.x, s[1][0]); s[1][1] = fmaf(a.y, bq.y, s[1][1]);
            s[1][2] = fmaf(a.y, bq.z, s[1][2]); s[1][3] = fmaf(a.y, bq.w, s[1][3]);
            s[2][0] = fmaf(a.z, bq.x, s[2][0]); s[2][1] = fmaf(a.z, bq.y, s[2][1]);
            s[2][2] = fmaf(a.z, bq.z, s[2][2]); s[2][3] = fmaf(a.z, bq.w, s[2][3]);
            s[3][0] = fmaf(a.w, bq.x, s[3][0]); s[3][1] = fmaf(a.w, bq.y, s[3][1]);
            s[3][2] = fmaf(a.w, bq.z, s[3][2]); s[3][3] = fmaf(a.w, bq.w, s[3][3]);
        }

        // scale + causal mask (only diagonal tile has masked entries)
#pragma unroll
        for (int i = 0; i < 4; i++)
#pragma unroll
            for (int j = 0; j < 4; j++) {
                float v = s[i][j] * scale;
                if (kt == qt && (tx*4 + j) > (ty*4 + i)) v = -1e30f;
                s[i][j] = v;
            }

        // online softmax update (row stats reduced across 16 tx lanes)
        float alpha[4];
#pragma unroll
        for (int i = 0; i < 4; i++) {
            float r = fmaxf(fmaxf(s[i][0], s[i][1]), fmaxf(s[i][2], s[i][3]));
            r = fmaxf(r, __shfl_xor_sync(0xffffffffu, r, 1));
            r = fmaxf(r, __shfl_xor_sync(0xffffffffu, r, 2));
            r = fmaxf(r, __shfl_xor_sync(0xffffffffu, r, 4));
            r = fmaxf(r, __shfl_xor_sync(0xffffffffu, r, 8));
            float mnew = fmaxf(m_i[i], r);
            float ps = 0.f;
#pragma unroll
            for (int j = 0; j < 4; j++) {
                float p = __expf(s[i][j] - mnew);
                s[i][j] = p;
                ps += p;
            }
            ps += __shfl_xor_sync(0xffffffffu, ps, 1);
            ps += __shfl_xor_sync(0xffffffffu, ps, 2);
            ps += __shfl_xor_sync(0xffffffffu, ps, 4);
            ps += __shfl_xor_sync(0xffffffffu, ps, 8);
            alpha[i] = __expf(m_i[i] - mnew);
            l_i[i] = l_i[i] * alpha[i] + ps;
            m_i[i] = mnew;
        }
#pragma unroll
        for (int i = 0; i < 4; i++)
#pragma unroll
            for (int j = 0; j < 4; j++) o[i][j] *= alpha[i];

        __syncthreads();           // all done reading Kt
#pragma unroll
        for (int i = 0; i < 4; i++) {
            float4 p4 = make_float4(s[i][0], s[i][1], s[i][2], s[i][3]);
            *(float4*)&KP[ty*4+i][tx*4] = p4;   // P[row][k]
        }
        __syncthreads();

        // O += P V   (contract over k=64)
#pragma unroll
        for (int k4 = 0; k4 < 16; k4++) {
            float4 bv0 = *(float4*)&Vs[k4*4+0][tx*4];
            float4 bv1 = *(float4*)&Vs[k4*4+1][tx*4];
            float4 bv2 = *(float4*)&Vs[k4*4+2][tx*4];
            float4 bv3 = *(float4*)&Vs[k4*4+3][tx*4];
#pragma unroll
            for (int i = 0; i < 4; i++) {
                float4 a = *(float4*)&KP[ty*4+i][k4*4];
                o[i][0] = fmaf(a.x, bv0.x, o[i][0]); o[i][1] = fmaf(a.x, bv0.y, o[i][1]);
                o[i][2] = fmaf(a.x, bv0.z, o[i][2]); o[i][3] = fmaf(a.x, bv0.w, o[i][3]);
                o[i][0] = fmaf(a.y, bv1.x, o[i][0]); o[i][1] = fmaf(a.y, bv1.y, o[i][1]);
                o[i][2] = fmaf(a.y, bv1.z, o[i][2]); o[i][3] = fmaf(a.y, bv1.w, o[i][3]);
                o[i][0] = fmaf(a.z, bv2.x, o[i][0]); o[i][1] = fmaf(a.z, bv2.y, o[i][1]);
                o[i][2] = fmaf(a.z, bv2.z, o[i][2]); o[i][3] = fmaf(a.z, bv2.w, o[i][3]);
                o[i][0] = fmaf(a.w, bv3.x, o[i][0]); o[i][1] = fmaf(a.w, bv3.y, o[i][1]);
                o[i][2] = fmaf(a.w, bv3.z, o[i][2]); o[i][3] = fmaf(a.w, bv3.w, o[i][3]);
            }
        }
    }

    // normalize + write attn output in [B,S,E] layout
#pragma unroll
    for (int i = 0; i < 4; i++) {
        float inv = 1.f / l_i[i];
        int rowg = qt*64 + ty*4 + i;
        float4 r = make_float4(o[i][0]*inv, o[i][1]*inv, o[i][2]*inv, o[i][3]*inv);
        *(float4*)(g_attn + ((size_t)b * S_ + rowg) * E_ + h * D_ + tx*4) = r;
    }
}

// ---------------------------------------------------------------------------
extern "C" void kernel_launch(void* const* d_in, const int* in_sizes, int n_in,
                              void* d_out, int out_size)
{
    const float* Q  = (const float*)d_in[0];
    const float* K  = (const float*)d_in[1];
    const float* V  = (const float*)d_in[2];
    const float* Wq = (const float*)d_in[3];
    const float* bq = (const float*)d_in[4];
    const float* Wk = (const float*)d_in[5];
    const float* bk = (const float*)d_in[6];
    const float* Wv = (const float*)d_in[7];
    const float* bv = (const float*)d_in[8];
    const float* Wo = (const float*)d_in[9];
    const float* bo = (const float*)d_in[10];
    // d_in[11] = mask: tril -> causal handled analytically

    float *qb, *kb, *vb, *ab;
    cudaGetSymbolAddress((void**)&qb, g_q);
    cudaGetSymbolAddress((void**)&kb, g_k);
    cudaGetSymbolAddress((void**)&vb, g_v);
    cudaGetSymbolAddress((void**)&ab, g_attn);

    dim3 gg(E_/128, M_/128);     // (8, 32)
    dim3 blk(256);
    gemm_bias_kernel<true><<<gg, blk>>>(Q, Wq, bq, qb);
    gemm_bias_kernel<true><<<gg, blk>>>(K, Wk, bk, kb);
    gemm_bias_kernel<true><<<gg, blk>>>(V, Wv, bv, vb);
    attn_kernel<<<dim3(S_/64, B_*H_), blk>>>();
    gemm_bias_kernel<false><<<gg, blk>>>(ab, Wo, bo, (float*)d_out);
}